// round 1
// baseline (speedup 1.0000x reference)
#include <cuda_runtime.h>
#include <math.h>

#define TT 8192
#define NE 1024
#define HH 64
#define BM 32
#define BN 64
#define NBLK (TT/BM)   /* 256 row-blocks */

__device__ float g_q[TT*HH];
__device__ float g_k[TT*HH];
__device__ float g_v[TT*HH];

// ---------------------------------------------------------------------------
// Projection: C[t,h] = sum_e X[t,e] * W[h,e]   (W is [64,1024] row-major)
// Block = 64 rows x 64 heads, K-chunks of 32, 256 threads, 4x4 microtile.
// ---------------------------------------------------------------------------
__global__ __launch_bounds__(256) void proj_kernel(
    const float* __restrict__ Xq, const float* __restrict__ Xk, const float* __restrict__ Xv,
    const float* __restrict__ Wq, const float* __restrict__ Wk, const float* __restrict__ Wv)
{
    const int p = blockIdx.y;
    const float* __restrict__ X = (p == 0) ? Xq : (p == 1) ? Xk : Xv;
    const float* __restrict__ W = (p == 0) ? Wq : (p == 1) ? Wk : Wv;
    float* C = (p == 0) ? g_q : (p == 1) ? g_k : g_v;
    const float scale = (p == 0) ? 0.125f : 1.0f;   // 1/sqrt(64) folded into q

    __shared__ float Xst[32][68];   // [k][row]  (transposed for vector LDS)
    __shared__ float Wst[32][68];   // [k][head]

    const int tid  = threadIdx.x;
    const int tx   = tid & 15;
    const int ty   = tid >> 4;
    const int row0 = blockIdx.x * 64;

    float acc[4][4];
#pragma unroll
    for (int i = 0; i < 4; i++)
#pragma unroll
        for (int j = 0; j < 4; j++) acc[i][j] = 0.f;

    for (int kc = 0; kc < NE; kc += 32) {
#pragma unroll
        for (int h2 = 0; h2 < 2; h2++) {
            const int f  = tid + h2 * 256;     // 0..511 float4 slots
            const int r  = f >> 3;             // 0..63
            const int k4 = (f & 7) << 2;       // 0,4,...,28
            float4 xv = *(const float4*)(X + (size_t)(row0 + r) * NE + kc + k4);
            Xst[k4 + 0][r] = xv.x; Xst[k4 + 1][r] = xv.y;
            Xst[k4 + 2][r] = xv.z; Xst[k4 + 3][r] = xv.w;
            float4 wv = *(const float4*)(W + (size_t)r * NE + kc + k4);
            Wst[k4 + 0][r] = wv.x; Wst[k4 + 1][r] = wv.y;
            Wst[k4 + 2][r] = wv.z; Wst[k4 + 3][r] = wv.w;
        }
        __syncthreads();
#pragma unroll
        for (int k = 0; k < 32; k++) {
            float4 a = *(const float4*)&Xst[k][ty << 2];
            float4 b = *(const float4*)&Wst[k][tx << 2];
            float av[4] = {a.x, a.y, a.z, a.w};
            float bv[4] = {b.x, b.y, b.z, b.w};
#pragma unroll
            for (int i = 0; i < 4; i++)
#pragma unroll
                for (int j = 0; j < 4; j++)
                    acc[i][j] += av[i] * bv[j];
        }
        __syncthreads();
    }

#pragma unroll
    for (int i = 0; i < 4; i++) {
        float4 o = make_float4(acc[i][0] * scale, acc[i][1] * scale,
                               acc[i][2] * scale, acc[i][3] * scale);
        *(float4*)(C + (size_t)(row0 + (ty << 2) + i) * HH + (tx << 2)) = o;
    }
}

// ---------------------------------------------------------------------------
// Causal flash attention, fp32.
// 128 threads/CTA, 4 threads per query row (16 dims each), BM=32 rows/block.
// CTA c processes row-blocks c and (255-c) -> perfectly balanced causal work.
// ---------------------------------------------------------------------------
__global__ __launch_bounds__(128) void attn_kernel(float* __restrict__ out)
{
    __shared__ float Ks[BN][HH];   // 16 KB
    __shared__ float Vs[BN][HH];   // 16 KB

    const int tid = threadIdx.x;
    const int rl  = tid >> 2;        // 0..31 local row
    const int sub = tid & 3;         // 0..3  dim-slice
    const int d0  = sub * 16;

#pragma unroll 1
    for (int piece = 0; piece < 2; piece++) {
        const int rb  = piece ? (NBLK - 1 - (int)blockIdx.x) : (int)blockIdx.x;
        const int row = rb * BM + rl;

        float q[16];
#pragma unroll
        for (int i = 0; i < 16; i += 4) {
            float4 t4 = *(const float4*)(g_q + (size_t)row * HH + d0 + i);
            q[i] = t4.x; q[i + 1] = t4.y; q[i + 2] = t4.z; q[i + 3] = t4.w;
        }
        float o[16];
#pragma unroll
        for (int i = 0; i < 16; i++) o[i] = 0.f;
        float m = -1e30f, l = 0.f;

        const int kv_end = rb * BM + BM;                 // causal bound
        const int ntiles = (kv_end + BN - 1) / BN;

        for (int t = 0; t < ntiles; t++) {
            const int j0 = t * BN;
            __syncthreads();       // previous tile fully consumed
            {
                const float4* kg = (const float4*)(g_k + (size_t)j0 * HH);
                const float4* vg = (const float4*)(g_v + (size_t)j0 * HH);
                float4* ks4 = (float4*)Ks;
                float4* vs4 = (float4*)Vs;
#pragma unroll
                for (int i = 0; i < 8; i++) {
                    ks4[tid + i * 128] = kg[tid + i * 128];
                    vs4[tid + i * 128] = vg[tid + i * 128];
                }
            }
            __syncthreads();

            const bool full = (j0 + BN <= row + 1);      // whole tile unmasked
#pragma unroll 1
            for (int cc = 0; cc < BN; cc += 16) {
                float s[16];
#pragma unroll
                for (int jj = 0; jj < 16; jj++) {
                    const float* kr = &Ks[cc + jj][d0];
                    float a = 0.f;
#pragma unroll
                    for (int i = 0; i < 16; i++) a += q[i] * kr[i];
                    a += __shfl_xor_sync(0xffffffffu, a, 1);
                    a += __shfl_xor_sync(0xffffffffu, a, 2);
                    if (!full && (j0 + cc + jj > row)) a = -INFINITY;
                    s[jj] = a;
                }
                float mloc = s[0];
#pragma unroll
                for (int jj = 1; jj < 16; jj++) mloc = fmaxf(mloc, s[jj]);
                const float mnew = fmaxf(m, mloc);
                const float fac  = __expf(m - mnew);
                l *= fac;
#pragma unroll
                for (int i = 0; i < 16; i++) o[i] *= fac;
#pragma unroll
                for (int jj = 0; jj < 16; jj++) {
                    const float pexp = __expf(s[jj] - mnew);
                    l += pexp;
                    const float* vr = &Vs[cc + jj][d0];
#pragma unroll
                    for (int i = 0; i < 16; i++) o[i] += pexp * vr[i];
                }
                m = mnew;
            }
        }

        const float inv = 1.0f / l;
#pragma unroll
        for (int i = 0; i < 16; i += 4) {
            float4 t4 = make_float4(o[i] * inv, o[i + 1] * inv,
                                    o[i + 2] * inv, o[i + 3] * inv);
            *(float4*)(out + (size_t)row * HH + d0 + i) = t4;
        }
    }
}

// ---------------------------------------------------------------------------
extern "C" void kernel_launch(void* const* d_in, const int* in_sizes, int n_in,
                              void* d_out, int out_size)
{
    const float* xq = (const float*)d_in[0];
    const float* xk = (const float*)d_in[1];
    const float* xv = (const float*)d_in[2];
    /* d_in[3] = mask: causal triu, reconstructed arithmetically (not read) */
    const float* wq = (const float*)d_in[4];
    const float* wk = (const float*)d_in[5];
    const float* wv = (const float*)d_in[6];
    float* out = (float*)d_out;

    dim3 pgrid(TT / 64, 3);
    proj_kernel<<<pgrid, 256>>>(xq, xk, xv, wq, wk, wv);
    attn_kernel<<<NBLK / 2, 128>>>(out);
    (void)in_sizes; (void)n_in; (void)out_size;
}

// round 2
// speedup vs baseline: 1.9026x; 1.9026x over previous
#include <cuda_runtime.h>
#include <math.h>

#define TT 8192
#define NE 1024
#define HH 64
#define BM 32
#define BN 64
#define NBLK (TT/BM)   /* 256 row-blocks */

__device__ float g_q[TT*HH];
__device__ float g_k[TT*HH];
__device__ float g_v[TT*HH];

// ---------------------------------------------------------------------------
// Projection: C[t,h] = sum_e X[t,e] * W[h,e]   (W is [64,1024] row-major)
// ---------------------------------------------------------------------------
__global__ __launch_bounds__(256) void proj_kernel(
    const float* __restrict__ Xq, const float* __restrict__ Xk, const float* __restrict__ Xv,
    const float* __restrict__ Wq, const float* __restrict__ Wk, const float* __restrict__ Wv)
{
    const int p = blockIdx.y;
    const float* __restrict__ X = (p == 0) ? Xq : (p == 1) ? Xk : Xv;
    const float* __restrict__ W = (p == 0) ? Wq : (p == 1) ? Wk : Wv;
    float* C = (p == 0) ? g_q : (p == 1) ? g_k : g_v;
    const float scale = (p == 0) ? 0.125f : 1.0f;   // 1/sqrt(64) folded into q

    __shared__ __align__(16) float Xst[32][68];   // [k][row]
    __shared__ __align__(16) float Wst[32][68];   // [k][head]

    const int tid  = threadIdx.x;
    const int tx   = tid & 15;
    const int ty   = tid >> 4;
    const int row0 = blockIdx.x * 64;

    float acc[4][4];
#pragma unroll
    for (int i = 0; i < 4; i++)
#pragma unroll
        for (int j = 0; j < 4; j++) acc[i][j] = 0.f;

    for (int kc = 0; kc < NE; kc += 32) {
#pragma unroll
        for (int h2 = 0; h2 < 2; h2++) {
            const int f  = tid + h2 * 256;
            const int r  = f >> 3;
            const int k4 = (f & 7) << 2;
            float4 xv = *(const float4*)(X + (size_t)(row0 + r) * NE + kc + k4);
            Xst[k4 + 0][r] = xv.x; Xst[k4 + 1][r] = xv.y;
            Xst[k4 + 2][r] = xv.z; Xst[k4 + 3][r] = xv.w;
            float4 wv = *(const float4*)(W + (size_t)r * NE + kc + k4);
            Wst[k4 + 0][r] = wv.x; Wst[k4 + 1][r] = wv.y;
            Wst[k4 + 2][r] = wv.z; Wst[k4 + 3][r] = wv.w;
        }
        __syncthreads();
#pragma unroll
        for (int k = 0; k < 32; k++) {
            float4 a = *(const float4*)&Xst[k][ty << 2];
            float4 b = *(const float4*)&Wst[k][tx << 2];
            float av[4] = {a.x, a.y, a.z, a.w};
            float bv[4] = {b.x, b.y, b.z, b.w};
#pragma unroll
            for (int i = 0; i < 4; i++)
#pragma unroll
                for (int j = 0; j < 4; j++)
                    acc[i][j] += av[i] * bv[j];
        }
        __syncthreads();
    }

#pragma unroll
    for (int i = 0; i < 4; i++) {
        float4 o = make_float4(acc[i][0] * scale, acc[i][1] * scale,
                               acc[i][2] * scale, acc[i][3] * scale);
        *(float4*)(C + (size_t)(row0 + (ty << 2) + i) * HH + (tx << 2)) = o;
    }
}

// ---------------------------------------------------------------------------
// Causal flash attention, fp32, register-tiled 4x4 microtiles.
// 128 threads: thread grid 8 (row groups) x 16 (col groups).
// One 32-row block per CTA; longest blocks launch first for balance.
// Smem (exactly 48KB): Qt[64][32], Kt[64][64], Vs[64][64], Pt[64][32].
// ---------------------------------------------------------------------------
__global__ __launch_bounds__(128) void attn_kernel(float* __restrict__ out)
{
    __shared__ __align__(16) float Qt[HH][BM];   // [dim][row]   8 KB
    __shared__ __align__(16) float Kt[HH][BN];   // [dim][col]  16 KB
    __shared__ __align__(16) float Vs[BN][HH];   // [col][dim]  16 KB
    __shared__ __align__(16) float Pt[BN][BM];   // [col][row]   8 KB

    const int tid = threadIdx.x;
    const int tx  = tid & 15;        // col group
    const int ty  = tid >> 4;        // row group 0..7
    const int rb  = NBLK - 1 - (int)blockIdx.x;   // longest first
    const int row0 = rb * BM;

    // Load Q block, transposed: Qt[d][r]
    {
        const int r  = tid & 31;
        const int dc = tid >> 5;               // 0..3
#pragma unroll
        for (int i = 0; i < 4; i++) {
            const int d4 = (dc + i * 4) << 2;  // dims d4..d4+3
            float4 q4 = *(const float4*)(g_q + (size_t)(row0 + r) * HH + d4);
            Qt[d4 + 0][r] = q4.x; Qt[d4 + 1][r] = q4.y;
            Qt[d4 + 2][r] = q4.z; Qt[d4 + 3][r] = q4.w;
        }
    }

    float o[4][4];
    float m_[4], l_[4];
#pragma unroll
    for (int i = 0; i < 4; i++) {
        m_[i] = -1e30f; l_[i] = 0.f;
#pragma unroll
        for (int j = 0; j < 4; j++) o[i][j] = 0.f;
    }

    const int ntiles = (row0 + BM + BN - 1) / BN;

    for (int t = 0; t < ntiles; t++) {
        const int j0 = t * BN;
        __syncthreads();
        // Load K transposed: Kt[d][c]
        {
            const int c  = tid & 63;
            const int dc = tid >> 6;           // 0..1
#pragma unroll
            for (int i = 0; i < 8; i++) {
                const int d4 = (dc + i * 2) << 2;
                float4 k4 = *(const float4*)(g_k + (size_t)(j0 + c) * HH + d4);
                Kt[d4 + 0][c] = k4.x; Kt[d4 + 1][c] = k4.y;
                Kt[d4 + 2][c] = k4.z; Kt[d4 + 3][c] = k4.w;
            }
            // Load V natural layout (fully coalesced)
            const float4* vg = (const float4*)(g_v + (size_t)j0 * HH);
            float4* vs4 = (float4*)Vs;
#pragma unroll
            for (int i = 0; i < 8; i++) vs4[tid + i * 128] = vg[tid + i * 128];
        }
        __syncthreads();

        // ---- S = Q @ K^T  (register 4x4 outer products) ----
        float s[4][4];
#pragma unroll
        for (int i = 0; i < 4; i++)
#pragma unroll
            for (int j = 0; j < 4; j++) s[i][j] = 0.f;

#pragma unroll 8
        for (int k = 0; k < HH; k++) {
            float4 a = *(const float4*)&Qt[k][ty << 2];
            float4 b = *(const float4*)&Kt[k][tx << 2];
            float av[4] = {a.x, a.y, a.z, a.w};
            float bv[4] = {b.x, b.y, b.z, b.w};
#pragma unroll
            for (int i = 0; i < 4; i++)
#pragma unroll
                for (int j = 0; j < 4; j++)
                    s[i][j] += av[i] * bv[j];
        }

        // ---- causal mask (only tiles overlapping the diagonal) ----
        if (j0 + BN > row0 + 1) {
#pragma unroll
            for (int i = 0; i < 4; i++) {
                const int row = row0 + (ty << 2) + i;
#pragma unroll
                for (int j = 0; j < 4; j++) {
                    if (j0 + (tx << 2) + j > row) s[i][j] = -INFINITY;
                }
            }
        }

        // ---- online softmax (row stats reduced across the 16 tx lanes) ----
#pragma unroll
        for (int i = 0; i < 4; i++) {
            float mloc = fmaxf(fmaxf(s[i][0], s[i][1]), fmaxf(s[i][2], s[i][3]));
#pragma unroll
            for (int w = 1; w < 16; w <<= 1)
                mloc = fmaxf(mloc, __shfl_xor_sync(0xffffffffu, mloc, w));
            const float mnew = fmaxf(m_[i], mloc);
            const float fac  = __expf(m_[i] - mnew);
            float psum = 0.f;
#pragma unroll
            for (int j = 0; j < 4; j++) {
                s[i][j] = __expf(s[i][j] - mnew);
                psum += s[i][j];
            }
#pragma unroll
            for (int w = 1; w < 16; w <<= 1)
                psum += __shfl_xor_sync(0xffffffffu, psum, w);
            l_[i] = l_[i] * fac + psum;
#pragma unroll
            for (int j = 0; j < 4; j++) o[i][j] *= fac;
            m_[i] = mnew;
        }

        // ---- store P transposed: Pt[c][r] ----
#pragma unroll
        for (int j = 0; j < 4; j++) {
            float4 p4 = make_float4(s[0][j], s[1][j], s[2][j], s[3][j]);
            *(float4*)&Pt[(tx << 2) + j][ty << 2] = p4;
        }
        __syncthreads();

        // ---- O += P @ V ----
#pragma unroll 8
        for (int j = 0; j < BN; j++) {
            float4 a = *(const float4*)&Pt[j][ty << 2];
            float4 b = *(const float4*)&Vs[j][tx << 2];
            float av[4] = {a.x, a.y, a.z, a.w};
            float bv[4] = {b.x, b.y, b.z, b.w};
#pragma unroll
            for (int i = 0; i < 4; i++)
#pragma unroll
                for (int h = 0; h < 4; h++)
                    o[i][h] += av[i] * bv[h];
        }
    }

    // ---- epilogue: normalize and store ----
#pragma unroll
    for (int i = 0; i < 4; i++) {
        const float inv = 1.0f / l_[i];
        float4 o4 = make_float4(o[i][0] * inv, o[i][1] * inv,
                                o[i][2] * inv, o[i][3] * inv);
        *(float4*)(out + (size_t)(row0 + (ty << 2) + i) * HH + (tx << 2)) = o4;
    }
}

// ---------------------------------------------------------------------------
extern "C" void kernel_launch(void* const* d_in, const int* in_sizes, int n_in,
                              void* d_out, int out_size)
{
    const float* xq = (const float*)d_in[0];
    const float* xk = (const float*)d_in[1];
    const float* xv = (const float*)d_in[2];
    /* d_in[3] = mask: causal triu, reconstructed arithmetically (not read) */
    const float* wq = (const float*)d_in[4];
    const float* wk = (const float*)d_in[5];
    const float* wv = (const float*)d_in[6];
    float* out = (float*)d_out;

    dim3 pgrid(TT / 64, 3);
    proj_kernel<<<pgrid, 256>>>(xq, xk, xv, wq, wk, wv);
    attn_kernel<<<NBLK, 128>>>(out);
    (void)in_sizes; (void)n_in; (void)out_size;
}